// round 16
// baseline (speedup 1.0000x reference)
#include <cuda_runtime.h>

// Convex upsampling (RAFT-style), R12: single balanced wave.
//
// Shapes:
//   flow: (4, 1, 160, 320) f32
//   mask: (4, 144, 160, 320) f32   (144 = 9 taps * 16 subpixels)
//   out:  (4, 1, 640, 1280) f32
//
// mask channel for tap k, subpixel (fy,fx): c = k*16 + fy*4 + fx
//
// R7/R10/R11 all pin at 5.25-5.27 TB/s across occ 52-85%, pipelined or not,
// 128B or 256B requests. Last uncontrolled variable: wave balance. R11 ran
// 3200 blocks over 1776 slots = 1.8 waves -> ~20% of slots idle for the
// second half (avg ~10% demand loss). This kernel: one thread handles BOTH
// fy-halves (fy and fy+2) of a w-pair -> 204800 threads = 1600 blocks x 128
// = a single wave (< 1776 slots), every thread identical work, no tail.
// Flow window loaded to smem once, reused by both fy groups.

#define NN 4
#define HH 160
#define WW 320
#define WP (WW / 2)    // 160 pairs per row
#define FF 4
#define OW (WW * FF)   // 1280
#define PLANE (HH * WW)

__global__ __launch_bounds__(128, 12) void convex_upsample_kernel(
    const float* __restrict__ flow,
    const float* __restrict__ mask,
    float* __restrict__ out)
{
    __shared__ float fvs[12][128];           // [dy*4+dx][tid], 3 rows x 4 cols

    int tid = threadIdx.x;
    int idx = blockIdx.x * 128 + tid;        // exact: 1600*128 = 204800

    int wp  = idx % WP;                      // pair index: pixels 2wp, 2wp+1
    int h   = (idx / WP) % HH;
    int fy0 = (idx / (WP * HH)) & 1;         // this thread: fy0 and fy0+2
    int n   = idx / (WP * HH * 2);
    int w0  = wp * 2;

    // ---- flow window rows h-1..h+1, cols w0-1..w0+2, zero-padded, x4 ----
    const float* fp = flow + (size_t)n * PLANE;
#pragma unroll
    for (int dy = 0; dy < 3; dy++) {
        int hh = h + dy - 1;
        bool hv = (hh >= 0 && hh < HH);
#pragma unroll
        for (int dx = 0; dx < 4; dx++) {
            int ww = w0 + dx - 1;
            float v = 0.0f;
            if (hv && ww >= 0 && ww < WW)
                v = 4.0f * fp[hh * WW + ww];
            fvs[dy * 4 + dx][tid] = v;
        }
    }
    // each thread reads only its own column -> no __syncthreads needed

    const float2* mbase = reinterpret_cast<const float2*>(
        mask + (size_t)n * 144 * PLANE + (size_t)h * WW + w0);
    float* obase = out + ((size_t)n * (FF * HH) + h * FF) * OW + wp * 8;

#pragma unroll
    for (int t = 0; t < 2; t++) {
        int fy = fy0 + t * 2;
        const float2* base = mbase + (size_t)(fy * 4) * (PLANE / 2);

        float r0[4], r1[4];
#pragma unroll
        for (int g = 0; g < 4; g++) {
            float2 mv[9];
#pragma unroll
            for (int k = 0; k < 9; k++)
                mv[k] = __ldcs(base + (size_t)(g + 16 * k) * (PLANE / 2));

            float sa = 0.0f, aa = 0.0f, sb = 0.0f, ab = 0.0f;
#pragma unroll
            for (int ky = 0; ky < 3; ky++) {
#pragma unroll
                for (int kx = 0; kx < 3; kx++) {
                    float2 m = mv[ky * 3 + kx];
                    float e0 = __expf(m.x);  // no max-sub: inputs ~N(0,1)
                    sa += e0;
                    aa = fmaf(e0, fvs[ky * 4 + kx][tid], aa);
                    float e1 = __expf(m.y);
                    sb += e1;
                    ab = fmaf(e1, fvs[ky * 4 + kx + 1][tid], ab);
                }
            }
            r0[g] = __fdividef(aa, sa);
            r1[g] = __fdividef(ab, sb);
        }

        // out row h*4+fy, cols [8wp, 8wp+8): two contiguous float4
        float* orow = obase + (size_t)fy * OW;
        __stcs(reinterpret_cast<float4*>(orow),
               make_float4(r0[0], r0[1], r0[2], r0[3]));
        __stcs(reinterpret_cast<float4*>(orow) + 1,
               make_float4(r1[0], r1[1], r1[2], r1[3]));
    }
}

extern "C" void kernel_launch(void* const* d_in, const int* in_sizes, int n_in,
                              void* d_out, int out_size)
{
    const float* flow = (const float*)d_in[0];
    const float* mask = (const float*)d_in[1];
    float* out = (float*)d_out;

    const int total = NN * 2 * HH * WP;       // 204800 threads
    const int threads = 128;
    const int blocks = total / threads;       // 1600 exact -> single wave
    convex_upsample_kernel<<<blocks, threads>>>(flow, mask, out);
}

// round 17
// speedup vs baseline: 1.0822x; 1.0822x over previous
#include <cuda_runtime.h>

// Convex upsampling (RAFT-style), R12: single balanced wave.
//
// Shapes:
//   flow: (4, 1, 160, 320) f32
//   mask: (4, 144, 160, 320) f32   (144 = 9 taps * 16 subpixels)
//   out:  (4, 1, 640, 1280) f32
//
// mask channel for tap k, subpixel (fy,fx): c = k*16 + fy*4 + fx
//
// R7/R10/R11 all pin at 5.25-5.27 TB/s across occ 52-85%, pipelined or not,
// 128B or 256B requests. Last uncontrolled variable: wave balance. R11 ran
// 3200 blocks over 1776 slots = 1.8 waves -> ~20% of slots idle for the
// second half (avg ~10% demand loss). This kernel: one thread handles BOTH
// fy-halves (fy and fy+2) of a w-pair -> 204800 threads = 1600 blocks x 128
// = a single wave (< 1776 slots), every thread identical work, no tail.
// Flow window loaded to smem once, reused by both fy groups.

#define NN 4
#define HH 160
#define WW 320
#define WP (WW / 2)    // 160 pairs per row
#define FF 4
#define OW (WW * FF)   // 1280
#define PLANE (HH * WW)

__global__ __launch_bounds__(128, 12) void convex_upsample_kernel(
    const float* __restrict__ flow,
    const float* __restrict__ mask,
    float* __restrict__ out)
{
    __shared__ float fvs[12][128];           // [dy*4+dx][tid], 3 rows x 4 cols

    int tid = threadIdx.x;
    int idx = blockIdx.x * 128 + tid;        // exact: 1600*128 = 204800

    int wp  = idx % WP;                      // pair index: pixels 2wp, 2wp+1
    int h   = (idx / WP) % HH;
    int fy0 = (idx / (WP * HH)) & 1;         // this thread: fy0 and fy0+2
    int n   = idx / (WP * HH * 2);
    int w0  = wp * 2;

    // ---- flow window rows h-1..h+1, cols w0-1..w0+2, zero-padded, x4 ----
    const float* fp = flow + (size_t)n * PLANE;
#pragma unroll
    for (int dy = 0; dy < 3; dy++) {
        int hh = h + dy - 1;
        bool hv = (hh >= 0 && hh < HH);
#pragma unroll
        for (int dx = 0; dx < 4; dx++) {
            int ww = w0 + dx - 1;
            float v = 0.0f;
            if (hv && ww >= 0 && ww < WW)
                v = 4.0f * fp[hh * WW + ww];
            fvs[dy * 4 + dx][tid] = v;
        }
    }
    // each thread reads only its own column -> no __syncthreads needed

    const float2* mbase = reinterpret_cast<const float2*>(
        mask + (size_t)n * 144 * PLANE + (size_t)h * WW + w0);
    float* obase = out + ((size_t)n * (FF * HH) + h * FF) * OW + wp * 8;

#pragma unroll
    for (int t = 0; t < 2; t++) {
        int fy = fy0 + t * 2;
        const float2* base = mbase + (size_t)(fy * 4) * (PLANE / 2);

        float r0[4], r1[4];
#pragma unroll
        for (int g = 0; g < 4; g++) {
            float2 mv[9];
#pragma unroll
            for (int k = 0; k < 9; k++)
                mv[k] = __ldcs(base + (size_t)(g + 16 * k) * (PLANE / 2));

            float sa = 0.0f, aa = 0.0f, sb = 0.0f, ab = 0.0f;
#pragma unroll
            for (int ky = 0; ky < 3; ky++) {
#pragma unroll
                for (int kx = 0; kx < 3; kx++) {
                    float2 m = mv[ky * 3 + kx];
                    float e0 = __expf(m.x);  // no max-sub: inputs ~N(0,1)
                    sa += e0;
                    aa = fmaf(e0, fvs[ky * 4 + kx][tid], aa);
                    float e1 = __expf(m.y);
                    sb += e1;
                    ab = fmaf(e1, fvs[ky * 4 + kx + 1][tid], ab);
                }
            }
            r0[g] = __fdividef(aa, sa);
            r1[g] = __fdividef(ab, sb);
        }

        // out row h*4+fy, cols [8wp, 8wp+8): two contiguous float4
        float* orow = obase + (size_t)fy * OW;
        __stcs(reinterpret_cast<float4*>(orow),
               make_float4(r0[0], r0[1], r0[2], r0[3]));
        __stcs(reinterpret_cast<float4*>(orow) + 1,
               make_float4(r1[0], r1[1], r1[2], r1[3]));
    }
}

extern "C" void kernel_launch(void* const* d_in, const int* in_sizes, int n_in,
                              void* d_out, int out_size)
{
    const float* flow = (const float*)d_in[0];
    const float* mask = (const float*)d_in[1];
    float* out = (float*)d_out;

    const int total = NN * 2 * HH * WP;       // 204800 threads
    const int threads = 128;
    const int blocks = total / threads;       // 1600 exact -> single wave
    convex_upsample_kernel<<<blocks, threads>>>(flow, mask, out);
}